// round 6
// baseline (speedup 1.0000x reference)
#include <cuda_runtime.h>

// FNO with global head. B=16, C=16, H=W=256, L=4, modes 16x16.
// Truncated separable DFT as register-tiled fp32 GEMMs; proj2+pool commuted.
// R6: xdft 8x4 tiles; ydft via transposed-T table; wsynth reverted to unfolded.

#define Bn 16
#define Cn 16
#define Hn 256
#define Wn 256
#define Ln 4
#define BCHW (Bn*Cn*Hn*Wn)

__device__ float g_v0[BCHW];                 // ping
__device__ float g_v1[BCHW];                 // pong
__device__ float g_a  [Bn*Cn*Hn*32];         // x-DFT result [row][2kx+ri]
__device__ float g_vft[Bn*Cn*32*32];         // retained modes [bc][m*32+kx*2+ri]
__device__ float g_gs [Bn*Cn*Hn*32];         // h-synth [bc*256+h][kx*2+ri]
__device__ float g_etab[256*32];             // xdft E: [w][2kx+ri] = (cos, -sin)
__device__ float g_xc[16*256];               // wsynth cos[kx][w]
__device__ float g_xs[16*256];               // wsynth sin[kx][w]
__device__ float g_E3[512*64];               // hsynth E3: [2h+ro][2m+p]
__device__ float g_Tt[512*64];               // ydft T transposed: [2h+p][2m+ri]
__device__ float g_pool[Bn*1024*128];        // proj partial sums

__device__ __forceinline__ float gelu_t(float x) {
    const float k0 = 0.7978845608028654f;
    const float k1 = 0.044715f;
    float y = k0 * x * (1.0f + k1 * x * x);
    float th;
    asm("tanh.approx.f32 %0, %1;" : "=f"(th) : "f"(y));
    return 0.5f * x * (1.0f + th);
}

// ---------------- build all constant tables ----------------
__global__ void k_tw() {
    int j = blockIdx.x * 256 + threadIdx.x;
    if (j < 8192) {                                   // g_etab
        int w = j >> 5, c = j & 31;
        int kx = c >> 1, ri = c & 1;
        float ang = (float)((kx * w) & 255) / 128.0f;
        g_etab[j] = ri ? -sinpif(ang) : cospif(ang);
    } else if (j < 12288) {                           // g_xc
        int e = j - 8192;
        int kx = e >> 8, w = e & 255;
        g_xc[e] = cospif((float)((kx * w) & 255) / 128.0f);
    } else if (j < 16384) {                           // g_xs
        int e = j - 12288;
        int kx = e >> 8, w = e & 255;
        g_xs[e] = sinpif((float)((kx * w) & 255) / 128.0f);
    } else if (j < 49152) {                           // g_E3 [2h+ro][2m+p]
        int e = j - 16384;
        int row = e >> 6, col = e & 63;
        int h = row >> 1, ro = row & 1;
        int m = col >> 1, p = col & 1;
        int ky = (m < 16) ? m : (m + 224);
        float ang = (float)((ky * h) & 255) / 128.0f;
        float cy = cospif(ang), sy = sinpif(ang);
        g_E3[e] = (ro == 0) ? (p == 0 ? cy : -sy) : (p == 0 ? sy : cy);
    } else if (j < 81920) {                           // g_Tt [2h+p][2m+ri]
        int e = j - 49152;
        int k = e >> 6, row = e & 63;
        int m = row >> 1, ri = row & 1;
        int h = k >> 1, p = k & 1;
        int ky = (m < 16) ? m : (m + 224);
        float ang = (float)((ky * h) & 255) / 128.0f;
        float cy = cospif(ang), sy = sinpif(ang);
        g_Tt[e] = (ri == 0) ? (p == 0 ? cy : sy) : (p == 0 ? -sy : cy);
    }
}

// ---------------- lifting 1 -> 16 channels ----------------
__global__ void k_lift(const float* __restrict__ x,
                       const float* __restrict__ lw,
                       const float* __restrict__ lb) {
    int idx = blockIdx.x * blockDim.x + threadIdx.x;
    int w = idx & 255;
    int h = (idx >> 8) & 255;
    int c = (idx >> 16) & 15;
    int b = idx >> 20;
    float xv = x[(b << 16) | (h << 8) | w];
    g_v0[idx] = lw[c] * xv + lb[c];
}

// ---------------- x-DFT GEMM: C[128 rows,32] = V[128,256] x E[256,32] ----
// 128 threads, thread tile 8 rows x 4 cols, K in chunks of 64. grid 512.
__global__ void __launch_bounds__(128) k_xdft(int flip) {
    __shared__ float vs[128][65];
    __shared__ float es[64][32];
    const float* __restrict__ vin = flip ? g_v1 : g_v0;
    int t = threadIdx.x;
    int rowbase = blockIdx.x * 128;
    const float* src = vin + (size_t)rowbase * 256;
    int rg = t >> 3, cg = t & 7;
    int r0 = rg * 8, c0 = cg * 4;
    float acc[8][4] = {};
    for (int wc = 0; wc < 4; wc++) {
        __syncthreads();
        for (int j = t; j < 2048; j += 128) {
            int r = j >> 4, q = j & 15;
            float4 v4 = *(const float4*)(src + r * 256 + wc * 64 + q * 4);
            vs[r][q * 4 + 0] = v4.x; vs[r][q * 4 + 1] = v4.y;
            vs[r][q * 4 + 2] = v4.z; vs[r][q * 4 + 3] = v4.w;
        }
        for (int j = t; j < 512; j += 128) {
            int k = j >> 3, q = j & 7;
            *(float4*)&es[k][q * 4] = *(const float4*)(g_etab + (wc * 64 + k) * 32 + q * 4);
        }
        __syncthreads();
        #pragma unroll 4
        for (int kk = 0; kk < 64; kk++) {
            float4 bf = *(const float4*)&es[kk][c0];
            #pragma unroll
            for (int i = 0; i < 8; i++) {
                float a = vs[r0 + i][kk];
                acc[i][0] += a * bf.x; acc[i][1] += a * bf.y;
                acc[i][2] += a * bf.z; acc[i][3] += a * bf.w;
            }
        }
    }
    #pragma unroll
    for (int i = 0; i < 8; i++)
        *(float4*)(g_a + (size_t)(rowbase + r0 + i) * 32 + c0) =
            make_float4(acc[i][0], acc[i][1], acc[i][2], acc[i][3]);
}

// ---------------- y-DFT per bc: C[64,16] = Tt^T x A, K=512 ---------------
// grid 256 (one bc), 128 threads; tile 4 rows x 2 kx.
__global__ void __launch_bounds__(128) k_ydft() {
    __shared__ float ts[64][68];      // [k in chunk][row]
    __shared__ float as[64][18];      // [k in chunk][kx]
    int t = threadIdx.x;
    int bc = blockIdx.x;
    int rg = t >> 3, cg = t & 7;
    int r0 = rg * 4;
    float acc[4][2] = {};
    for (int ch = 0; ch < 8; ch++) {
        int h0 = ch * 32, k0 = ch * 64;
        __syncthreads();
        for (int j = t; j < 1024; j += 128) {
            int kk = j >> 4, q = j & 15;
            *(float4*)&ts[kk][q * 4] = *(const float4*)(g_Tt + (size_t)(k0 + kk) * 64 + q * 4);
        }
        for (int j = t; j < 256; j += 128) {
            int hh = j >> 3, q = j & 7;
            float4 v4 = *(const float4*)(g_a + (size_t)(bc * 256 + h0 + hh) * 32 + q * 4);
            as[2 * hh + 0][2 * q + 0] = v4.x;
            as[2 * hh + 1][2 * q + 0] = v4.y;
            as[2 * hh + 0][2 * q + 1] = v4.z;
            as[2 * hh + 1][2 * q + 1] = v4.w;
        }
        __syncthreads();
        #pragma unroll 8
        for (int kk = 0; kk < 64; kk++) {
            float4 a4 = *(const float4*)&ts[kk][r0];
            float2 b2 = *(const float2*)&as[kk][2 * cg];
            acc[0][0] += a4.x * b2.x; acc[0][1] += a4.x * b2.y;
            acc[1][0] += a4.y * b2.x; acc[1][1] += a4.y * b2.y;
            acc[2][0] += a4.z * b2.x; acc[2][1] += a4.z * b2.y;
            acc[3][0] += a4.w * b2.x; acc[3][1] += a4.w * b2.y;
        }
    }
    #pragma unroll
    for (int i = 0; i < 4; i++) {
        int r = r0 + i, m = r >> 1, ri = r & 1;
        #pragma unroll
        for (int j = 0; j < 2; j++) {
            int kx = 2 * cg + j;
            g_vft[(size_t)bc * 1024 + m * 32 + kx * 2 + ri] = acc[i][j];
        }
    }
}

// ---------------- fused mix (16x16 complex per mode) + h-synthesis -------
// grid 256 = (b, o); 256 threads.
__global__ void __launch_bounds__(256) k_mixh(const float* __restrict__ w1r,
                                              const float* __restrict__ w1i,
                                              const float* __restrict__ w2r,
                                              const float* __restrict__ w2i,
                                              int l) {
    __shared__ float mixT[16][68];    // [kx][2m+p]
    int t = threadIdx.x;
    int b = blockIdx.x >> 4, o = blockIdx.x & 15;
    int bc = blockIdx.x;
    #pragma unroll
    for (int v = 0; v < 2; v++) {
        int idx = t + v * 256;
        int m = idx >> 4, kx = idx & 15, mm = m & 15;
        const float* wr = (m < 16) ? w1r : w2r;
        const float* wi = (m < 16) ? w1i : w2i;
        float accr = 0.f, acci = 0.f;
        #pragma unroll
        for (int i = 0; i < 16; i++) {
            const float2 vv = *(const float2*)(g_vft + (size_t)(b * 16 + i) * 1024 + m * 32 + kx * 2);
            int widx = (((l * 16 + i) * 16 + o) * 256) + mm * 16 + kx;
            float wrv = wr[widx], wiv = wi[widx];
            accr += vv.x * wrv - vv.y * wiv;
            acci += vv.x * wiv + vv.y * wrv;
        }
        mixT[kx][2 * m + 0] = accr;
        mixT[kx][2 * m + 1] = acci;
    }
    __syncthreads();
    int rg = t >> 3, cg = t & 7;
    float acc[16][2] = {};
    for (int ks = 0; ks < 64; ks += 4) {
        float4 bf0 = *(const float4*)&mixT[cg * 2 + 0][ks];
        float4 bf1 = *(const float4*)&mixT[cg * 2 + 1][ks];
        #pragma unroll
        for (int i = 0; i < 16; i++) {
            float4 af = *(const float4*)(g_E3 + (size_t)(32 * i + rg) * 64 + ks);
            acc[i][0] += af.x * bf0.x + af.y * bf0.y + af.z * bf0.z + af.w * bf0.w;
            acc[i][1] += af.x * bf1.x + af.y * bf1.y + af.z * bf1.z + af.w * bf1.w;
        }
    }
    #pragma unroll
    for (int i = 0; i < 16; i++) {
        int r = 32 * i + rg, h = r >> 1, ro = r & 1;
        #pragma unroll
        for (int jj = 0; jj < 2; jj++) {
            int kx = cg * 2 + jj;
            float sc = (kx == 0) ? (1.0f / 65536.0f) : (2.0f / 65536.0f);
            g_gs[(size_t)(bc * 256 + h) * 32 + kx * 2 + ro] = acc[i][jj] * sc;
        }
    }
}

// ---------------- fused w-synth + skip + gelu: [16,48]x[48,256] ----------
__global__ void __launch_bounds__(256) k_wsynth(const float* __restrict__ skw,
                         const float* __restrict__ skb,
                         int l, int act, int flip) {
    __shared__ float vs[16][256];
    __shared__ float ms[16][52];      // [o][0:16 skw | 16:32 gr | 32:48 -gi]
    __shared__ float sb[16];
    const float* __restrict__ vin = flip ? g_v1 : g_v0;
    float* __restrict__ vout = flip ? g_v0 : g_v1;
    int t = threadIdx.x;
    int b = blockIdx.x >> 8, h = blockIdx.x & 255;
    for (int j = t; j < 1024; j += 256) {
        int c = j >> 6, q = j & 63;
        *(float4*)&vs[c][q * 4] =
            *(const float4*)(vin + ((size_t)(b * 16 + c) * 256 + h) * 256 + q * 4);
    }
    {
        int c = t >> 4, k = t & 15;
        ms[c][k] = skw[l * 256 + c * 16 + k];
        int base = ((size_t)(b * 16 + c) * 256 + h) * 32 + k * 2;
        ms[c][16 + k] = g_gs[base];
        ms[c][32 + k] = -g_gs[base + 1];
        if (t < 16) sb[t] = skb[l * 16 + t];
    }
    __syncthreads();
    int og = t >> 6, wg = t & 63;
    int o0 = og * 4, w0 = wg * 4;
    float acc[4][4];
    #pragma unroll
    for (int i = 0; i < 4; i++) {
        float bv = sb[o0 + i];
        acc[i][0] = bv; acc[i][1] = bv; acc[i][2] = bv; acc[i][3] = bv;
    }
    #pragma unroll
    for (int k = 0; k < 16; k++) {
        float4 bf = *(const float4*)&vs[k][w0];
        #pragma unroll
        for (int i = 0; i < 4; i++) {
            float a = ms[o0 + i][k];
            acc[i][0] += a * bf.x; acc[i][1] += a * bf.y;
            acc[i][2] += a * bf.z; acc[i][3] += a * bf.w;
        }
    }
    #pragma unroll
    for (int kx = 0; kx < 16; kx++) {
        float4 bf = *(const float4*)(g_xc + kx * 256 + w0);
        #pragma unroll
        for (int i = 0; i < 4; i++) {
            float a = ms[o0 + i][16 + kx];
            acc[i][0] += a * bf.x; acc[i][1] += a * bf.y;
            acc[i][2] += a * bf.z; acc[i][3] += a * bf.w;
        }
    }
    #pragma unroll
    for (int kx = 0; kx < 16; kx++) {
        float4 bf = *(const float4*)(g_xs + kx * 256 + w0);
        #pragma unroll
        for (int i = 0; i < 4; i++) {
            float a = ms[o0 + i][32 + kx];
            acc[i][0] += a * bf.x; acc[i][1] += a * bf.y;
            acc[i][2] += a * bf.z; acc[i][3] += a * bf.w;
        }
    }
    #pragma unroll
    for (int i = 0; i < 4; i++) {
        float4 r;
        if (act) {
            r.x = gelu_t(acc[i][0]); r.y = gelu_t(acc[i][1]);
            r.z = gelu_t(acc[i][2]); r.w = gelu_t(acc[i][3]);
        } else {
            r.x = acc[i][0]; r.y = acc[i][1]; r.z = acc[i][2]; r.w = acc[i][3];
        }
        *(float4*)(vout + ((size_t)(b * 16 + o0 + i) * 256 + h) * 256 + w0) = r;
    }
}

// ---------------- proj1 (16->128) + gelu + partial pooling ----------------
__global__ void __launch_bounds__(128) k_proj(const float* __restrict__ w1,
                                              const float* __restrict__ b1) {
    __shared__ float4 vs4[16][16];
    __shared__ float red[4][128];
    int t = threadIdx.x;
    int blk = blockIdx.x;                 // b*1024 + h*4 + wc
    int wc = blk & 3, h = (blk >> 2) & 255, b = blk >> 10;
    const float* vrow = g_v0 + ((size_t)(b * 16) * 256 + h) * 256 + wc * 64;
    for (int j = t; j < 256; j += 128) {
        int i = j >> 4, p4 = j & 15;
        vs4[i][p4] = ((const float4*)(vrow + (size_t)i * 65536))[p4];
    }
    __syncthreads();
    int oc = t & 31, psub = t >> 5;
    int o0 = oc * 4;
    float wreg[4][16];
    #pragma unroll
    for (int j = 0; j < 4; j++)
        #pragma unroll
        for (int i = 0; i < 16; i++)
            wreg[j][i] = w1[(o0 + j) * 16 + i];
    float bb[4];
    #pragma unroll
    for (int j = 0; j < 4; j++) bb[j] = b1[o0 + j];
    float acc[4] = {0, 0, 0, 0};
    #pragma unroll
    for (int pg = 0; pg < 4; pg++) {
        float4 s[4];
        #pragma unroll
        for (int j = 0; j < 4; j++) s[j] = make_float4(bb[j], bb[j], bb[j], bb[j]);
        #pragma unroll
        for (int i = 0; i < 16; i++) {
            float4 v = vs4[i][psub * 4 + pg];
            #pragma unroll
            for (int j = 0; j < 4; j++) {
                s[j].x += wreg[j][i] * v.x;
                s[j].y += wreg[j][i] * v.y;
                s[j].z += wreg[j][i] * v.z;
                s[j].w += wreg[j][i] * v.w;
            }
        }
        #pragma unroll
        for (int j = 0; j < 4; j++)
            acc[j] += gelu_t(s[j].x) + gelu_t(s[j].y) + gelu_t(s[j].z) + gelu_t(s[j].w);
    }
    #pragma unroll
    for (int j = 0; j < 4; j++) red[psub][o0 + j] = acc[j];
    __syncthreads();
    if (t < 128) {
        float s = red[0][t] + red[1][t] + red[2][t] + red[3][t];
        g_pool[(size_t)blk * 128 + t] = s;
    }
}

// ---------------- final reduce + proj2 on pooled vector + head -----------
__global__ void k_head(const float* __restrict__ w2, const float* __restrict__ b2,
                       const float* __restrict__ hw_, const float* __restrict__ hb,
                       float* __restrict__ out) {
    __shared__ float pq[128];
    __shared__ float f[64];
    int b = blockIdx.x, t = threadIdx.x;
    float s = 0.f;
    for (int k = 0; k < 1024; k++)
        s += g_pool[((size_t)(b * 1024 + k)) * 128 + t];
    pq[t] = s * (1.0f / 65536.0f);
    __syncthreads();
    if (t < 64) {
        float a = b2[t];
        #pragma unroll 8
        for (int i = 0; i < 128; i++) a += w2[t * 128 + i] * pq[i];
        f[t] = a;
    }
    __syncthreads();
    if (t < 2) {
        float a = hb[t];
        #pragma unroll
        for (int o = 0; o < 64; o++) a += hw_[t * 64 + o] * f[o];
        float e = __expf(2.0f * a);
        out[b * 2 + t] = 1.0f - 2.0f / (e + 1.0f);
    }
}

extern "C" void kernel_launch(void* const* d_in, const int* in_sizes, int n_in,
                              void* d_out, int out_size) {
    const float* x    = (const float*)d_in[0];
    const float* lw   = (const float*)d_in[1];
    const float* lb   = (const float*)d_in[2];
    const float* w1r  = (const float*)d_in[3];
    const float* w1i  = (const float*)d_in[4];
    const float* w2r  = (const float*)d_in[5];
    const float* w2i  = (const float*)d_in[6];
    const float* skw  = (const float*)d_in[7];
    const float* skb  = (const float*)d_in[8];
    const float* pw1  = (const float*)d_in[9];
    const float* pb1  = (const float*)d_in[10];
    const float* pw2  = (const float*)d_in[11];
    const float* pb2  = (const float*)d_in[12];
    const float* hw_  = (const float*)d_in[13];
    const float* hb   = (const float*)d_in[14];
    float* out = (float*)d_out;

    k_tw<<<320, 256>>>();
    k_lift<<<BCHW / 256, 256>>>(x, lw, lb);
    for (int l = 0; l < Ln; l++) {
        int flip = l & 1;                    // input buffer: 0 -> g_v0
        k_xdft  <<<512, 128>>>(flip);
        k_ydft  <<<256, 128>>>();
        k_mixh  <<<256, 256>>>(w1r, w1i, w2r, w2i, l);
        k_wsynth<<<4096, 256>>>(skw, skb, l, (l < Ln - 1) ? 1 : 0, flip);
    }
    // after 4 layers result is in g_v0
    k_proj<<<16384, 128>>>(pw1, pb1);
    k_head<<<Bn, 128>>>(pw2, pb2, hw_, hb, out);
}

// round 7
// speedup vs baseline: 1.0608x; 1.0608x over previous
#include <cuda_runtime.h>

// FNO with global head. B=16, C=16, H=W=256, L=4, modes 16x16.
// Truncated separable DFT as register-tiled fp32 GEMMs; proj2+pool commuted.
// R7: exact R3 build + ydft K-split(4) across blocks (partials summed in mix).

#define Bn 16
#define Cn 16
#define Hn 256
#define Wn 256
#define Ln 4
#define BCHW (Bn*Cn*Hn*Wn)

__device__ float g_v0[BCHW];                 // ping
__device__ float g_v1[BCHW];                 // pong
__device__ float g_a  [Bn*Cn*Hn*32];         // x-DFT result [row][2kx+ri]
__device__ float g_vftp[4*Bn*Cn*1024];       // ydft partials [ks][bc][m*32+kx*2+ri]
__device__ float g_mix[Bn*Cn*32*32];         // after channel mix
__device__ float g_gs [Bn*Cn*Hn*32];         // h-synth [bc*256+h][kx*2+ri]
__device__ float g_etab[256*32];             // xdft E: [w][2kx+ri] = (cos, -sin)
__device__ float g_xc[16*256];               // wsynth cos[kx][w]
__device__ float g_xs[16*256];               // wsynth sin[kx][w]
__device__ float g_T [64*512];               // ydft T: [2m+ri][2h+p]
__device__ float g_E3[512*64];               // hsynth E3: [2h+ro][2m+p]
__device__ float g_pool[Bn*1024*128];        // proj partial sums

__device__ __forceinline__ float gelu_t(float x) {
    const float k0 = 0.7978845608028654f;
    const float k1 = 0.044715f;
    float y = k0 * x * (1.0f + k1 * x * x);
    float th;
    asm("tanh.approx.f32 %0, %1;" : "=f"(th) : "f"(y));
    return 0.5f * x * (1.0f + th);
}

// ---------------- build all constant tables ----------------
__global__ void k_tw() {
    int j = blockIdx.x * 256 + threadIdx.x;
    if (j < 8192) {                                   // g_etab
        int w = j >> 5, c = j & 31;
        int kx = c >> 1, ri = c & 1;
        float ang = (float)((kx * w) & 255) / 128.0f;
        g_etab[j] = ri ? -sinpif(ang) : cospif(ang);
    } else if (j < 12288) {                           // g_xc
        int e = j - 8192;
        int kx = e >> 8, w = e & 255;
        g_xc[e] = cospif((float)((kx * w) & 255) / 128.0f);
    } else if (j < 16384) {                           // g_xs
        int e = j - 12288;
        int kx = e >> 8, w = e & 255;
        g_xs[e] = sinpif((float)((kx * w) & 255) / 128.0f);
    } else if (j < 49152) {                           // g_T [2m+ri][2h+p]
        int e = j - 16384;
        int row = e >> 9, col = e & 511;
        int m = row >> 1, ri = row & 1;
        int h = col >> 1, p = col & 1;
        int ky = (m < 16) ? m : (m + 224);
        float ang = (float)((ky * h) & 255) / 128.0f;
        float cy = cospif(ang), sy = sinpif(ang);
        g_T[e] = (ri == 0) ? (p == 0 ? cy : sy) : (p == 0 ? -sy : cy);
    } else if (j < 81920) {                           // g_E3 [2h+ro][2m+p]
        int e = j - 49152;
        int row = e >> 6, col = e & 63;
        int h = row >> 1, ro = row & 1;
        int m = col >> 1, p = col & 1;
        int ky = (m < 16) ? m : (m + 224);
        float ang = (float)((ky * h) & 255) / 128.0f;
        float cy = cospif(ang), sy = sinpif(ang);
        g_E3[e] = (ro == 0) ? (p == 0 ? cy : -sy) : (p == 0 ? sy : cy);
    }
}

// ---------------- lifting 1 -> 16 channels ----------------
__global__ void k_lift(const float* __restrict__ x,
                       const float* __restrict__ lw,
                       const float* __restrict__ lb) {
    int idx = blockIdx.x * blockDim.x + threadIdx.x;
    int w = idx & 255;
    int h = (idx >> 8) & 255;
    int c = (idx >> 16) & 15;
    int b = idx >> 20;
    float xv = x[(b << 16) | (h << 8) | w];
    g_v0[idx] = lw[c] * xv + lb[c];
}

// ---------------- x-DFT GEMM: C[64 rows,32] = V[64,256] x E[256,32] ------
__global__ void __launch_bounds__(128) k_xdft(int flip) {
    __shared__ float vs[64][65];
    __shared__ float es[64][32];
    const float* __restrict__ vin = flip ? g_v1 : g_v0;
    int t = threadIdx.x;
    int rowbase = blockIdx.x * 64;
    const float* src = vin + (size_t)rowbase * 256;
    int rg = t >> 3, cg = t & 7;
    int r0 = rg * 4, c0 = cg * 4;
    float acc[4][4] = {};
    for (int wc = 0; wc < 4; wc++) {
        __syncthreads();
        for (int j = t; j < 1024; j += 128) {
            int r = j >> 4, q = j & 15;
            float4 v4 = *(const float4*)(src + r * 256 + wc * 64 + q * 4);
            vs[r][q * 4 + 0] = v4.x; vs[r][q * 4 + 1] = v4.y;
            vs[r][q * 4 + 2] = v4.z; vs[r][q * 4 + 3] = v4.w;
        }
        for (int j = t; j < 512; j += 128) {
            int k = j >> 3, q = j & 7;
            *(float4*)&es[k][q * 4] = *(const float4*)(g_etab + (wc * 64 + k) * 32 + q * 4);
        }
        __syncthreads();
        #pragma unroll 8
        for (int kk = 0; kk < 64; kk++) {
            float a0 = vs[r0 + 0][kk], a1 = vs[r0 + 1][kk];
            float a2 = vs[r0 + 2][kk], a3 = vs[r0 + 3][kk];
            float4 bf = *(const float4*)&es[kk][c0];
            acc[0][0] += a0 * bf.x; acc[0][1] += a0 * bf.y; acc[0][2] += a0 * bf.z; acc[0][3] += a0 * bf.w;
            acc[1][0] += a1 * bf.x; acc[1][1] += a1 * bf.y; acc[1][2] += a1 * bf.z; acc[1][3] += a1 * bf.w;
            acc[2][0] += a2 * bf.x; acc[2][1] += a2 * bf.y; acc[2][2] += a2 * bf.z; acc[2][3] += a2 * bf.w;
            acc[3][0] += a3 * bf.x; acc[3][1] += a3 * bf.y; acc[3][2] += a3 * bf.z; acc[3][3] += a3 * bf.w;
        }
    }
    #pragma unroll
    for (int i = 0; i < 4; i++)
        *(float4*)(g_a + (size_t)(rowbase + r0 + i) * 32 + c0) =
            make_float4(acc[i][0], acc[i][1], acc[i][2], acc[i][3]);
}

// ---------------- y-DFT GEMM, K-split x4: per (2bc, ks): partial C --------
// grid 512 = (bc/2) * 4 ksplits; 128 threads; tile 4x4.
__global__ void __launch_bounds__(128) k_ydft() {
    __shared__ float ts[64][65];      // [k within chunk][out row]
    __shared__ float as[64][36];      // [k within chunk][col = bcq*16+kx]
    int t = threadIdx.x;
    int ks = blockIdx.x & 3;
    int bc0 = (blockIdx.x >> 2) * 2;
    int rg = t >> 3, cg = t & 7;
    int r0 = rg * 4, c0 = cg * 4;
    float acc[4][4] = {};
    for (int ci = 0; ci < 2; ci++) {
        int ch = ks * 2 + ci;
        int h0 = ch * 32, k0 = ch * 64;
        __syncthreads();
        for (int j = t; j < 1024; j += 128) {
            int row = j >> 4, q = j & 15;
            float4 v4 = *(const float4*)(g_T + row * 512 + k0 + q * 4);
            ts[q * 4 + 0][row] = v4.x; ts[q * 4 + 1][row] = v4.y;
            ts[q * 4 + 2][row] = v4.z; ts[q * 4 + 3][row] = v4.w;
        }
        for (int j = t; j < 512; j += 128) {
            int bcq = j >> 8, rem = j & 255, hh = rem >> 3, q = rem & 7;
            float4 v4 = *(const float4*)(g_a + (size_t)((bc0 + bcq) * 256 + h0 + hh) * 32 + q * 4);
            int n0 = bcq * 16 + q * 2;
            as[2 * hh + 0][n0] = v4.x;     as[2 * hh + 1][n0] = v4.y;
            as[2 * hh + 0][n0 + 1] = v4.z; as[2 * hh + 1][n0 + 1] = v4.w;
        }
        __syncthreads();
        #pragma unroll 8
        for (int kk = 0; kk < 64; kk++) {
            float a0 = ts[kk][r0 + 0], a1 = ts[kk][r0 + 1];
            float a2 = ts[kk][r0 + 2], a3 = ts[kk][r0 + 3];
            float4 bf = *(const float4*)&as[kk][c0];
            acc[0][0] += a0 * bf.x; acc[0][1] += a0 * bf.y; acc[0][2] += a0 * bf.z; acc[0][3] += a0 * bf.w;
            acc[1][0] += a1 * bf.x; acc[1][1] += a1 * bf.y; acc[1][2] += a1 * bf.z; acc[1][3] += a1 * bf.w;
            acc[2][0] += a2 * bf.x; acc[2][1] += a2 * bf.y; acc[2][2] += a2 * bf.z; acc[2][3] += a2 * bf.w;
            acc[3][0] += a3 * bf.x; acc[3][1] += a3 * bf.y; acc[3][2] += a3 * bf.z; acc[3][3] += a3 * bf.w;
        }
    }
    float* vout = g_vftp + (size_t)ks * (Bn * Cn * 1024);
    #pragma unroll
    for (int i = 0; i < 4; i++) {
        int r = r0 + i, m = r >> 1, ri = r & 1;
        #pragma unroll
        for (int j = 0; j < 4; j++) {
            int c = c0 + j, bcq = c >> 4, kx = c & 15;
            vout[(bc0 + bcq) * 1024 + m * 32 + kx * 2 + ri] = acc[i][j];
        }
    }
}

// ---------------- per-mode 16x16 complex channel mixing (sums partials) --
__global__ void k_mix(const float* __restrict__ w1r, const float* __restrict__ w1i,
                      const float* __restrict__ w2r, const float* __restrict__ w2i,
                      int l) {
    int tid = blockIdx.x * blockDim.x + threadIdx.x;   // 131072
    int kx = tid & 15;
    int m = (tid >> 4) & 31;
    int o = (tid >> 9) & 15;
    int b = tid >> 13;
    int mm = m & 15;
    const float* wr = (m < 16) ? w1r : w2r;
    const float* wi = (m < 16) ? w1i : w2i;
    const int P = Bn * Cn * 1024;
    float accr = 0.f, acci = 0.f;
    #pragma unroll
    for (int i = 0; i < 16; i++) {
        int vidx = (b * 16 + i) * 1024 + m * 32 + kx * 2;
        float2 p0 = *(const float2*)(g_vftp + vidx);
        float2 p1 = *(const float2*)(g_vftp + P + vidx);
        float2 p2 = *(const float2*)(g_vftp + 2 * P + vidx);
        float2 p3 = *(const float2*)(g_vftp + 3 * P + vidx);
        float vr = (p0.x + p1.x) + (p2.x + p3.x);
        float vv = (p0.y + p1.y) + (p2.y + p3.y);
        int widx = (((l * 16 + i) * 16 + o) * 256) + mm * 16 + kx;
        float wrv = wr[widx], wiv = wi[widx];
        accr += vr * wrv - vv * wiv;
        acci += vr * wiv + vv * wrv;
    }
    int outi = (b * 16 + o) * 1024 + m * 32 + kx * 2;
    g_mix[outi + 0] = accr;
    g_mix[outi + 1] = acci;
}

// ---------------- h-synthesis GEMM per bc: C[512,16] = E3[512,64] x M ----
__global__ void __launch_bounds__(256) k_hsynth() {
    __shared__ float mixT[16][68];    // [kx][2m+p]
    int t = threadIdx.x;
    int bc = blockIdx.x;
    {
        float4 v4 = *(const float4*)(g_mix + (size_t)bc * 1024 + t * 4);
        int i4 = t * 4;
        #pragma unroll
        for (int e = 0; e < 4; e++) {
            int idx = i4 + e;
            int m = idx >> 5, rem = idx & 31, kx = rem >> 1, p = rem & 1;
            float val = (e == 0) ? v4.x : (e == 1) ? v4.y : (e == 2) ? v4.z : v4.w;
            mixT[kx][2 * m + p] = val;
        }
    }
    __syncthreads();
    int rg = t >> 3, cg = t & 7;
    float acc[16][2] = {};
    for (int ks = 0; ks < 64; ks += 4) {
        float4 bf0 = *(const float4*)&mixT[cg * 2 + 0][ks];
        float4 bf1 = *(const float4*)&mixT[cg * 2 + 1][ks];
        #pragma unroll
        for (int i = 0; i < 16; i++) {
            float4 af = *(const float4*)(g_E3 + (size_t)(32 * i + rg) * 64 + ks);
            acc[i][0] += af.x * bf0.x + af.y * bf0.y + af.z * bf0.z + af.w * bf0.w;
            acc[i][1] += af.x * bf1.x + af.y * bf1.y + af.z * bf1.z + af.w * bf1.w;
        }
    }
    #pragma unroll
    for (int i = 0; i < 16; i++) {
        int r = 32 * i + rg, h = r >> 1, ro = r & 1;
        #pragma unroll
        for (int jj = 0; jj < 2; jj++) {
            int kx = cg * 2 + jj;
            float sc = (kx == 0) ? (1.0f / 65536.0f) : (2.0f / 65536.0f);
            g_gs[(size_t)(bc * 256 + h) * 32 + kx * 2 + ro] = acc[i][jj] * sc;
        }
    }
}

// ---------------- fused w-synth + skip + gelu: [16,48]x[48,256] ----------
__global__ void __launch_bounds__(256) k_wsynth(const float* __restrict__ skw,
                         const float* __restrict__ skb,
                         int l, int act, int flip) {
    __shared__ float vs[16][256];
    __shared__ float ms[16][52];      // [o][0:16 skw | 16:32 gr | 32:48 -gi]
    __shared__ float sb[16];
    const float* __restrict__ vin = flip ? g_v1 : g_v0;
    float* __restrict__ vout = flip ? g_v0 : g_v1;
    int t = threadIdx.x;
    int b = blockIdx.x >> 8, h = blockIdx.x & 255;
    for (int j = t; j < 1024; j += 256) {
        int c = j >> 6, q = j & 63;
        *(float4*)&vs[c][q * 4] =
            *(const float4*)(vin + ((size_t)(b * 16 + c) * 256 + h) * 256 + q * 4);
    }
    {
        int c = t >> 4, k = t & 15;
        ms[c][k] = skw[l * 256 + c * 16 + k];
        int base = ((size_t)(b * 16 + c) * 256 + h) * 32 + k * 2;
        ms[c][16 + k] = g_gs[base];
        ms[c][32 + k] = -g_gs[base + 1];
        if (t < 16) sb[t] = skb[l * 16 + t];
    }
    __syncthreads();
    int og = t >> 6, wg = t & 63;
    int o0 = og * 4, w0 = wg * 4;
    float acc[4][4];
    #pragma unroll
    for (int i = 0; i < 4; i++) {
        float bv = sb[o0 + i];
        acc[i][0] = bv; acc[i][1] = bv; acc[i][2] = bv; acc[i][3] = bv;
    }
    #pragma unroll
    for (int k = 0; k < 16; k++) {
        float4 bf = *(const float4*)&vs[k][w0];
        #pragma unroll
        for (int i = 0; i < 4; i++) {
            float a = ms[o0 + i][k];
            acc[i][0] += a * bf.x; acc[i][1] += a * bf.y;
            acc[i][2] += a * bf.z; acc[i][3] += a * bf.w;
        }
    }
    #pragma unroll
    for (int kx = 0; kx < 16; kx++) {
        float4 bf = *(const float4*)(g_xc + kx * 256 + w0);
        #pragma unroll
        for (int i = 0; i < 4; i++) {
            float a = ms[o0 + i][16 + kx];
            acc[i][0] += a * bf.x; acc[i][1] += a * bf.y;
            acc[i][2] += a * bf.z; acc[i][3] += a * bf.w;
        }
    }
    #pragma unroll
    for (int kx = 0; kx < 16; kx++) {
        float4 bf = *(const float4*)(g_xs + kx * 256 + w0);
        #pragma unroll
        for (int i = 0; i < 4; i++) {
            float a = ms[o0 + i][32 + kx];
            acc[i][0] += a * bf.x; acc[i][1] += a * bf.y;
            acc[i][2] += a * bf.z; acc[i][3] += a * bf.w;
        }
    }
    #pragma unroll
    for (int i = 0; i < 4; i++) {
        float4 r;
        if (act) {
            r.x = gelu_t(acc[i][0]); r.y = gelu_t(acc[i][1]);
            r.z = gelu_t(acc[i][2]); r.w = gelu_t(acc[i][3]);
        } else {
            r.x = acc[i][0]; r.y = acc[i][1]; r.z = acc[i][2]; r.w = acc[i][3];
        }
        *(float4*)(vout + ((size_t)(b * 16 + o0 + i) * 256 + h) * 256 + w0) = r;
    }
}

// ---------------- proj1 (16->128) + gelu + partial pooling ----------------
__global__ void __launch_bounds__(128) k_proj(const float* __restrict__ w1,
                                              const float* __restrict__ b1) {
    __shared__ float4 vs4[16][16];
    __shared__ float red[4][128];
    int t = threadIdx.x;
    int blk = blockIdx.x;                 // b*1024 + h*4 + wc
    int wc = blk & 3, h = (blk >> 2) & 255, b = blk >> 10;
    const float* vrow = g_v0 + ((size_t)(b * 16) * 256 + h) * 256 + wc * 64;
    for (int j = t; j < 256; j += 128) {
        int i = j >> 4, p4 = j & 15;
        vs4[i][p4] = ((const float4*)(vrow + (size_t)i * 65536))[p4];
    }
    __syncthreads();
    int oc = t & 31, psub = t >> 5;
    int o0 = oc * 4;
    float wreg[4][16];
    #pragma unroll
    for (int j = 0; j < 4; j++)
        #pragma unroll
        for (int i = 0; i < 16; i++)
            wreg[j][i] = w1[(o0 + j) * 16 + i];
    float bb[4];
    #pragma unroll
    for (int j = 0; j < 4; j++) bb[j] = b1[o0 + j];
    float acc[4] = {0, 0, 0, 0};
    #pragma unroll
    for (int pg = 0; pg < 4; pg++) {
        float4 s[4];
        #pragma unroll
        for (int j = 0; j < 4; j++) s[j] = make_float4(bb[j], bb[j], bb[j], bb[j]);
        #pragma unroll
        for (int i = 0; i < 16; i++) {
            float4 v = vs4[i][psub * 4 + pg];
            #pragma unroll
            for (int j = 0; j < 4; j++) {
                s[j].x += wreg[j][i] * v.x;
                s[j].y += wreg[j][i] * v.y;
                s[j].z += wreg[j][i] * v.z;
                s[j].w += wreg[j][i] * v.w;
            }
        }
        #pragma unroll
        for (int j = 0; j < 4; j++)
            acc[j] += gelu_t(s[j].x) + gelu_t(s[j].y) + gelu_t(s[j].z) + gelu_t(s[j].w);
    }
    #pragma unroll
    for (int j = 0; j < 4; j++) red[psub][o0 + j] = acc[j];
    __syncthreads();
    if (t < 128) {
        float s = red[0][t] + red[1][t] + red[2][t] + red[3][t];
        g_pool[(size_t)blk * 128 + t] = s;
    }
}

// ---------------- final reduce + proj2 on pooled vector + head -----------
__global__ void k_head(const float* __restrict__ w2, const float* __restrict__ b2,
                       const float* __restrict__ hw_, const float* __restrict__ hb,
                       float* __restrict__ out) {
    __shared__ float pq[128];
    __shared__ float f[64];
    int b = blockIdx.x, t = threadIdx.x;
    float s = 0.f;
    for (int k = 0; k < 1024; k++)
        s += g_pool[((size_t)(b * 1024 + k)) * 128 + t];
    pq[t] = s * (1.0f / 65536.0f);
    __syncthreads();
    if (t < 64) {
        float a = b2[t];
        #pragma unroll 8
        for (int i = 0; i < 128; i++) a += w2[t * 128 + i] * pq[i];
        f[t] = a;
    }
    __syncthreads();
    if (t < 2) {
        float a = hb[t];
        #pragma unroll
        for (int o = 0; o < 64; o++) a += hw_[t * 64 + o] * f[o];
        float e = __expf(2.0f * a);
        out[b * 2 + t] = 1.0f - 2.0f / (e + 1.0f);
    }
}

extern "C" void kernel_launch(void* const* d_in, const int* in_sizes, int n_in,
                              void* d_out, int out_size) {
    const float* x    = (const float*)d_in[0];
    const float* lw   = (const float*)d_in[1];
    const float* lb   = (const float*)d_in[2];
    const float* w1r  = (const float*)d_in[3];
    const float* w1i  = (const float*)d_in[4];
    const float* w2r  = (const float*)d_in[5];
    const float* w2i  = (const float*)d_in[6];
    const float* skw  = (const float*)d_in[7];
    const float* skb  = (const float*)d_in[8];
    const float* pw1  = (const float*)d_in[9];
    const float* pb1  = (const float*)d_in[10];
    const float* pw2  = (const float*)d_in[11];
    const float* pb2  = (const float*)d_in[12];
    const float* hw_  = (const float*)d_in[13];
    const float* hb   = (const float*)d_in[14];
    float* out = (float*)d_out;

    k_tw<<<320, 256>>>();
    k_lift<<<BCHW / 256, 256>>>(x, lw, lb);
    for (int l = 0; l < Ln; l++) {
        int flip = l & 1;                    // input buffer: 0 -> g_v0
        k_xdft  <<<1024, 128>>>(flip);
        k_ydft  <<<512, 128>>>();
        k_mix   <<<512, 256>>>(w1r, w1i, w2r, w2i, l);
        k_hsynth<<<256, 256>>>();
        k_wsynth<<<4096, 256>>>(skw, skb, l, (l < Ln - 1) ? 1 : 0, flip);
    }
    // after 4 layers result is in g_v0
    k_proj<<<16384, 128>>>(pw1, pb1);
    k_head<<<Bn, 128>>>(pw2, pb2, hw_, hb, out);
}